// round 14
// baseline (speedup 1.0000x reference)
#include <cuda_runtime.h>
#include <cuda_fp16.h>
#include <math.h>
#include <stdint.h>

#define BB 2
#define SS 2048
#define HH 32
#define DHH 128
#define NQ 4096
#define BSZ 4096
#define TK 64
#define NT 32
#define OSPLIT 8

// -------- scratch --------
__device__ float  g_part [OSPLIT*BSZ*DHH];
__device__ __half g_xh   [BSZ*DHH];
__device__ __half g_xkh  [BSZ*DHH];
__device__ __half g_xvh  [BSZ*DHH];
__device__ __half g_wqT  [NQ*DHH];
__device__ __half g_wkT  [DHH*DHH];
__device__ __half g_wvT  [DHH*DHH];
__device__ __half g_woT  [DHH*NQ];
__device__ __half g_qh   [BSZ*NQ];           // Q proj, log2e/sqrt(d) pre-scaled
__device__ __half g_kh   [BSZ*DHH];
__device__ __half g_vh   [BSZ*DHH];
__device__ __half g_attnh[BSZ*NQ];

// -------- helpers --------
__device__ __forceinline__ uint32_t smem_u32(const void* p){
    uint32_t a;
    asm("{ .reg .u64 t; cvta.to.shared.u64 t, %1; cvt.u32.u64 %0, t; }" : "=r"(a) : "l"(p));
    return a;
}
__device__ __forceinline__ void cp16(uint32_t dst, const void* src){
    asm volatile("cp.async.cg.shared.global [%0], [%1], 16;" :: "r"(dst), "l"(src));
}
#define CP_COMMIT() asm volatile("cp.async.commit_group;" ::: "memory")
#define CP_WAIT1()  asm volatile("cp.async.wait_group 1;" ::: "memory")
#define CP_WAIT0()  asm volatile("cp.async.wait_group 0;" ::: "memory")

__device__ __forceinline__ void mma16816(float* c, const uint32_t* a, const uint32_t* b){
    asm volatile("mma.sync.aligned.m16n8k16.row.col.f32.f16.f16.f32 "
        "{%0,%1,%2,%3}, {%4,%5,%6,%7}, {%8,%9}, {%0,%1,%2,%3};"
        : "+f"(c[0]), "+f"(c[1]), "+f"(c[2]), "+f"(c[3])
        : "r"(a[0]), "r"(a[1]), "r"(a[2]), "r"(a[3]), "r"(b[0]), "r"(b[1]));
}
__device__ __forceinline__ void ldsm4(uint32_t* r, uint32_t a){
    asm volatile("ldmatrix.sync.aligned.m8n8.x4.shared.b16 {%0,%1,%2,%3}, [%4];"
        : "=r"(r[0]), "=r"(r[1]), "=r"(r[2]), "=r"(r[3]) : "r"(a));
}
__device__ __forceinline__ void ldsm4t(uint32_t* r, uint32_t a){
    asm volatile("ldmatrix.sync.aligned.m8n8.x4.trans.shared.b16 {%0,%1,%2,%3}, [%4];"
        : "=r"(r[0]), "=r"(r[1]), "=r"(r[2]), "=r"(r[3]) : "r"(a));
}
__device__ __forceinline__ uint32_t packh2(float x, float y){
    __half2 h = __floats2half2_rn(x, y);
    return *reinterpret_cast<uint32_t*>(&h);
}
__device__ __forceinline__ uint32_t ex2x2(uint32_t h){
    uint32_t r;
    asm("ex2.approx.f16x2 %0, %1;" : "=r"(r) : "r"(h));
    return r;
}
__device__ __forceinline__ float sumh2(uint32_t h){
    __half2 v = *reinterpret_cast<__half2*>(&h);
    float2 f = __half22float2(v);
    return f.x + f.y;
}

// =======================================================================
// Fused prep: input converts (blocks 0..511) + weight transposes (512..1567)
// =======================================================================
__global__ __launch_bounds__(256) void prep_all(
    const float4* __restrict__ q, const float4* __restrict__ k, const float4* __restrict__ v,
    uint2* __restrict__ oq, uint2* __restrict__ ok, uint2* __restrict__ ov,
    const float* __restrict__ Wq, const float* __restrict__ Wk,
    const float* __restrict__ Wv, const float* __restrict__ Wo,
    __half* __restrict__ wqT, __half* __restrict__ wkT,
    __half* __restrict__ wvT, __half* __restrict__ woT)
{
    __shared__ float t[32][33];
    int id = blockIdx.x;
    if (id < 512) {
        int i = id * 256 + threadIdx.x;
        float4 f;
        f = q[i]; oq[i] = make_uint2(packh2(f.x, f.y), packh2(f.z, f.w));
        f = k[i]; ok[i] = make_uint2(packh2(f.x, f.y), packh2(f.z, f.w));
        f = v[i]; ov[i] = make_uint2(packh2(f.x, f.y), packh2(f.z, f.w));
        return;
    }
    id -= 512;
    const float* in; __half* out; int K, N, tile;
    if (id < 512)      { in = Wq; out = wqT; K = DHH; N = NQ;  tile = id; }
    else if (id < 528) { in = Wk; out = wkT; K = DHH; N = DHH; tile = id - 512; }
    else if (id < 544) { in = Wv; out = wvT; K = DHH; N = DHH; tile = id - 528; }
    else               { in = Wo; out = woT; K = NQ;  N = DHH; tile = id - 544; }
    int ntx = N / 32;
    int bx = (tile % ntx) * 32, by = (tile / ntx) * 32;
    int x = threadIdx.x & 31, y = threadIdx.x >> 5;
    #pragma unroll
    for (int i = 0; i < 4; ++i)
        t[y + 8*i][x] = in[(size_t)(by + y + 8*i)*N + bx + x];
    __syncthreads();
    #pragma unroll
    for (int i = 0; i < 4; ++i)
        out[(size_t)(bx + y + 8*i)*K + by + x] = __float2half_rn(t[x][y + 8*i]);
}

// =======================================================================
// Fused Q/K/V projections: one launch, flat grid of 1088 CTAs.
// =======================================================================
__global__ __launch_bounds__(256) void hgemm_qkv(
    const __half* __restrict__ xq, const __half* __restrict__ xk, const __half* __restrict__ xv,
    const __half* __restrict__ wqT, const __half* __restrict__ wkT, const __half* __restrict__ wvT,
    const float* __restrict__ b_q, const float* __restrict__ b_k, const float* __restrict__ b_v,
    __half* __restrict__ qh, __half* __restrict__ kh, __half* __restrict__ vh,
    float scl2)
{
    __shared__ __align__(16) __half As[2][128*40];
    __shared__ __align__(16) __half Bs[2][128*40];

    const int bid = blockIdx.x;
    const __half *A, *Bt; const float* bias; __half* C; int N, m0, n0; float scale;
    if (bid < 1024) {
        A = xq; Bt = wqT; bias = b_q; C = qh; N = NQ; scale = scl2;
        m0 = (bid >> 5) * 128; n0 = (bid & 31) * 128;
    } else if (bid < 1056) {
        A = xk; Bt = wkT; bias = b_k; C = kh; N = DHH; scale = 1.0f;
        m0 = (bid - 1024) * 128; n0 = 0;
    } else {
        A = xv; Bt = wvT; bias = b_v; C = vh; N = DHH; scale = 1.0f;
        m0 = (bid - 1056) * 128; n0 = 0;
    }

    const int tid = threadIdx.x, lane = tid & 31, w = tid >> 5;
    const int wm = (w >> 2) * 64, wn = (w & 3) * 32;
    const int g = lane >> 2, q4 = lane & 3;
    const int arow = ((lane >> 3) & 1) * 8 + (lane & 7);
    const int akse = (lane >> 4) * 8;
    const int brow = ((lane >> 4) & 1) * 8 + (lane & 7);
    const int bkse = ((lane >> 3) & 1) * 8;

    float acc[4][4][4] = {};

    auto load = [&](int kb, int st){
        #pragma unroll
        for (int i = 0; i < 2; ++i) {
            int e = tid + 256*i, r = e >> 2, c = e & 3;
            cp16(smem_u32(&As[st][r*40 + c*8]), A  + (size_t)(m0 + r)*DHH + kb*32 + c*8);
            cp16(smem_u32(&Bs[st][r*40 + c*8]), Bt + (size_t)(n0 + r)*DHH + kb*32 + c*8);
        }
    };
    load(0, 0); CP_COMMIT();

    #pragma unroll
    for (int kb = 0; kb < 4; ++kb) {
        if (kb + 1 < 4) { load(kb+1, (kb+1)&1); CP_COMMIT(); CP_WAIT1(); }
        else            { CP_WAIT0(); }
        __syncthreads();
        const int st = kb & 1;
        const uint32_t aB = smem_u32(&As[st][0]) + (wm + arow)*80 + akse*2;
        const uint32_t bB = smem_u32(&Bs[st][0]) + (wn + brow)*80 + bkse*2;
        #pragma unroll
        for (int ks = 0; ks < 2; ++ks) {
            uint32_t aF[4][4], bF[2][4];
            #pragma unroll
            for (int mi = 0; mi < 4; ++mi) ldsm4(aF[mi], aB + mi*16*80 + ks*32);
            #pragma unroll
            for (int np = 0; np < 2; ++np) ldsm4(bF[np], bB + np*16*80 + ks*32);
            #pragma unroll
            for (int mi = 0; mi < 4; ++mi)
                #pragma unroll
                for (int ni = 0; ni < 4; ++ni)
                    mma16816(acc[mi][ni], aF[mi], bF[ni>>1] + (ni&1)*2);
        }
        __syncthreads();
    }

    #pragma unroll
    for (int mi = 0; mi < 4; ++mi)
        #pragma unroll
        for (int ni = 0; ni < 4; ++ni) {
            int row = m0 + wm + mi*16 + g;
            int col = n0 + wn + ni*8 + 2*q4;
            float b0 = bias[col], b1 = bias[col+1];
            *reinterpret_cast<__half2*>(C + (size_t)row*N + col) =
                __floats2half2_rn((acc[mi][ni][0] + b0)*scale, (acc[mi][ni][1] + b1)*scale);
            *reinterpret_cast<__half2*>(C + (size_t)(row+8)*N + col) =
                __floats2half2_rn((acc[mi][ni][2] + b0)*scale, (acc[mi][ni][3] + b1)*scale);
        }
}

// ---- split-K hgemm + reduce (O projection), OSPLIT=8 ----
__global__ __launch_bounds__(256) void hgemm_splitk(
    const __half* __restrict__ A, const __half* __restrict__ Bt,
    float* __restrict__ part, int M, int N, int K)
{
    __shared__ __align__(16) __half As[2][128*40];
    __shared__ __align__(16) __half Bs[2][128*40];
    const int tid = threadIdx.x, lane = tid & 31, w = tid >> 5;
    const int wm = (w >> 2) * 64, wn = (w & 3) * 32;
    const int m0 = blockIdx.y * 128, n0 = blockIdx.x * 128;
    const int kc = blockIdx.z;
    const int g = lane >> 2, q4 = lane & 3;
    const int arow = ((lane >> 3) & 1) * 8 + (lane & 7);
    const int akse = (lane >> 4) * 8;
    const int brow = ((lane >> 4) & 1) * 8 + (lane & 7);
    const int bkse = ((lane >> 3) & 1) * 8;

    float acc[4][4][4] = {};
    const int nkpc = K / 32 / OSPLIT;
    const int kb0 = kc * nkpc;

    auto load = [&](int kb, int st){
        #pragma unroll
        for (int i = 0; i < 2; ++i) {
            int e = tid + 256*i, r = e >> 2, c = e & 3;
            cp16(smem_u32(&As[st][r*40 + c*8]), A  + (size_t)(m0 + r)*K + kb*32 + c*8);
            cp16(smem_u32(&Bs[st][r*40 + c*8]), Bt + (size_t)(n0 + r)*K + kb*32 + c*8);
        }
    };
    load(kb0, 0); CP_COMMIT();

    for (int i = 0; i < nkpc; ++i) {
        if (i + 1 < nkpc) { load(kb0+i+1, (i+1)&1); CP_COMMIT(); CP_WAIT1(); }
        else              { CP_WAIT0(); }
        __syncthreads();
        const int st = i & 1;
        const uint32_t aB = smem_u32(&As[st][0]) + (wm + arow)*80 + akse*2;
        const uint32_t bB = smem_u32(&Bs[st][0]) + (wn + brow)*80 + bkse*2;
        #pragma unroll
        for (int ks = 0; ks < 2; ++ks) {
            uint32_t aF[4][4], bF[2][4];
            #pragma unroll
            for (int mi = 0; mi < 4; ++mi) ldsm4(aF[mi], aB + mi*16*80 + ks*32);
            #pragma unroll
            for (int np = 0; np < 2; ++np) ldsm4(bF[np], bB + np*16*80 + ks*32);
            #pragma unroll
            for (int mi = 0; mi < 4; ++mi)
                #pragma unroll
                for (int ni = 0; ni < 4; ++ni)
                    mma16816(acc[mi][ni], aF[mi], bF[ni>>1] + (ni&1)*2);
        }
        __syncthreads();
    }

    float* P = part + (size_t)kc * M * N;
    #pragma unroll
    for (int mi = 0; mi < 4; ++mi)
        #pragma unroll
        for (int ni = 0; ni < 4; ++ni) {
            int row = m0 + wm + mi*16 + g;
            int col = n0 + wn + ni*8 + 2*q4;
            *reinterpret_cast<float2*>(P + (size_t)row*N + col)     = make_float2(acc[mi][ni][0], acc[mi][ni][1]);
            *reinterpret_cast<float2*>(P + (size_t)(row+8)*N + col) = make_float2(acc[mi][ni][2], acc[mi][ni][3]);
        }
}

__global__ void reduce_bias(const float* __restrict__ part, const float* __restrict__ bias,
                            float* __restrict__ out, int MN, int N)
{
    int i = (blockIdx.x * 256 + threadIdx.x) * 4;
    if (i >= MN) return;
    float4 s = *reinterpret_cast<const float4*>(part + i);
    #pragma unroll
    for (int kc = 1; kc < OSPLIT; ++kc) {
        float4 p = *reinterpret_cast<const float4*>(part + (size_t)kc*MN + i);
        s.x += p.x; s.y += p.y; s.z += p.z; s.w += p.w;
    }
    int c = i & (N - 1);
    s.x += bias[c]; s.y += bias[c+1]; s.z += bias[c+2]; s.w += bias[c+3];
    *reinterpret_cast<float4*>(out + i) = s;
}

// =======================================================================
// HMMA flash attention — Q fragments in REGISTERS (no Q smem / no Q ldsm),
// 3-stage K/V pipeline with single sync/tile, 2 CTAs/SM.
// LDS per warp-tile drops 80 -> 64 ldsm4 (the crossbar is the bottleneck).
// =======================================================================
#define KROWB 272
#define KBYTES (64*KROWB)
#define BUF    (2*KBYTES)             // K+V one stage: 34816
#define QROWS  128
#define SMEM_DYN (3*BUF)              // 104448 -> 2 CTAs/SM

__device__ __forceinline__ void load_tile(uint32_t buf, int b, int kt,
    const __half* kh, const __half* vh, int tid)
{
    const __half* ks = kh + ((size_t)b*SS + (size_t)kt*TK) * DHH;
    const __half* vs = vh + ((size_t)b*SS + (size_t)kt*TK) * DHH;
    #pragma unroll
    for (int t = 0; t < 8; ++t) {
        int e = tid + t*128, r = e >> 4, c = e & 15;
        cp16(buf + r*KROWB + c*16,          ks + (size_t)r*DHH + c*8);
        cp16(buf + KBYTES + r*KROWB + c*16, vs + (size_t)r*DHH + c*8);
    }
}

__global__ __launch_bounds__(128, 2) void attn_hmma(
    const __half* __restrict__ qh, const __half* __restrict__ kh,
    const __half* __restrict__ vh, __half* __restrict__ o2h)
{
    extern __shared__ __align__(16) char smraw[];
    const uint32_t kvb = smem_u32(smraw);
    const int qb = blockIdx.x, h = blockIdx.y, b = blockIdx.z;
    const int tid = threadIdx.x, w = tid >> 5, lane = tid & 31;
    const int g = lane >> 2, q4 = lane & 3;
    const int jrow = ((lane >> 4) & 1) * 8 + (lane & 7);
    const int ksel = ((lane >> 3) & 1) * 8;
    const int vrow = lane & 15;
    const int vcol8 = (lane >> 4) * 8;

    load_tile(kvb, b, 0, kh, vh, tid);
    CP_COMMIT();
    load_tile(kvb + BUF, b, 1, kh, vh, tid);
    CP_COMMIT();

    // Q fragments straight from gmem, held in registers for the whole kernel
    const __half* qsrc = qh + ((size_t)b*SS + (size_t)h*64 + (size_t)qb*4) * NQ;
    uint32_t aQ[2][8][4];
    #pragma unroll
    for (int m = 0; m < 2; ++m) {
        const int r0 = w*32 + m*16 + g, r1 = r0 + 8;
        #pragma unroll
        for (int ks = 0; ks < 8; ++ks) {
            const int d0 = 16*ks + 2*q4;
            aQ[m][ks][0] = *reinterpret_cast<const uint32_t*>(qsrc + (size_t)r0*DHH + d0);
            aQ[m][ks][1] = *reinterpret_cast<const uint32_t*>(qsrc + (size_t)r1*DHH + d0);
            aQ[m][ks][2] = *reinterpret_cast<const uint32_t*>(qsrc + (size_t)r0*DHH + d0 + 8);
            aQ[m][ks][3] = *reinterpret_cast<const uint32_t*>(qsrc + (size_t)r1*DHH + d0 + 8);
        }
    }

    float o[2][16][4];
    #pragma unroll
    for (int m = 0; m < 2; ++m)
        #pragma unroll
        for (int n = 0; n < 16; ++n)
            #pragma unroll
            for (int i = 0; i < 4; ++i) o[m][n][i] = 0.f;
    float rs[2][2] = {};

    for (int kt = 0; kt < NT; ++kt) {
        if (kt + 1 < NT) { CP_WAIT1(); } else { CP_WAIT0(); }
        __syncthreads();                     // single sync per tile (3 stages)
        if (kt + 2 < NT) {
            load_tile(kvb + (uint32_t)((kt+2)%3)*BUF, b, kt+2, kh, vh, tid);
            CP_COMMIT();
        }

        const uint32_t Kb = kvb + (uint32_t)(kt%3)*BUF + jrow*KROWB + ksel*2;
        const uint32_t Vb = kvb + (uint32_t)(kt%3)*BUF + KBYTES + vrow*KROWB + vcol8*2;

        // S phase restructured: jp outer (16-key group), ks inner.
        // K fragment shared by both m-tiles; score transient is only 16 regs.
        uint32_t P[2][4][4];
        #pragma unroll
        for (int jp = 0; jp < 4; ++jp) {
            float s[2][2][4] = {};
            uint32_t bb[2][4];
            const uint32_t Kj = Kb + jp*16*KROWB;
            ldsm4(bb[0], Kj);
            #pragma unroll
            for (int ks = 0; ks < 8; ++ks) {
                if (ks < 7) ldsm4(bb[(ks+1)&1], Kj + 32*(ks+1));
                mma16816(s[0][0], aQ[0][ks], bb[ks&1]);
                mma16816(s[0][1], aQ[0][ks], bb[ks&1] + 2);
                mma16816(s[1][0], aQ[1][ks], bb[ks&1]);
                mma16816(s[1][1], aQ[1][ks], bb[ks&1] + 2);
            }
            #pragma unroll
            for (int m = 0; m < 2; ++m) {
                uint32_t p0 = ex2x2(packh2(s[m][0][0], s[m][0][1]));
                uint32_t p1 = ex2x2(packh2(s[m][0][2], s[m][0][3]));
                uint32_t p2 = ex2x2(packh2(s[m][1][0], s[m][1][1]));
                uint32_t p3 = ex2x2(packh2(s[m][1][2], s[m][1][3]));
                P[m][jp][0] = p0; P[m][jp][1] = p1;
                P[m][jp][2] = p2; P[m][jp][3] = p3;
                rs[m][0] += sumh2(p0) + sumh2(p2);
                rs[m][1] += sumh2(p1) + sumh2(p3);
            }
        }

        // O += P V
        #pragma unroll
        for (int ks = 0; ks < 4; ++ks) {
            const uint32_t Vk = Vb + ks*16*KROWB;
            uint32_t bb[2][4];
            ldsm4t(bb[0], Vk);
            #pragma unroll
            for (int np = 0; np < 8; ++np) {
                if (np < 7) ldsm4t(bb[(np+1)&1], Vk + (np+1)*32);
                mma16816(o[0][2*np],   P[0][ks], bb[np&1]);
                mma16816(o[0][2*np+1], P[0][ks], bb[np&1] + 2);
                mma16816(o[1][2*np],   P[1][ks], bb[np&1]);
                mma16816(o[1][2*np+1], P[1][ks], bb[np&1] + 2);
            }
        }
    }

    // cross-lane rowsum reduce (4 lanes per row)
    #pragma unroll
    for (int m = 0; m < 2; ++m)
        #pragma unroll
        for (int r = 0; r < 2; ++r) {
            rs[m][r] += __shfl_xor_sync(0xffffffffu, rs[m][r], 1);
            rs[m][r] += __shfl_xor_sync(0xffffffffu, rs[m][r], 2);
        }

    // epilogue: rows = qb*128 + w*32 + m*16 + {g, g+8}
    #pragma unroll
    for (int m = 0; m < 2; ++m) {
        const float inv0 = 1.0f / rs[m][0], inv1 = 1.0f / rs[m][1];
        const int lr = w*32 + m*16 + g;
        __half* dst0 = o2h + ((size_t)b*SS + (size_t)qb*QROWS + lr)     * NQ + (size_t)h * DHH;
        __half* dst1 = o2h + ((size_t)b*SS + (size_t)qb*QROWS + lr + 8) * NQ + (size_t)h * DHH;
        #pragma unroll
        for (int n = 0; n < 16; ++n) {
            int c = 8*n + 2*q4;
            *reinterpret_cast<__half2*>(dst0 + c) = __floats2half2_rn(o[m][n][0]*inv0, o[m][n][1]*inv0);
            *reinterpret_cast<__half2*>(dst1 + c) = __floats2half2_rn(o[m][n][2]*inv1, o[m][n][3]*inv1);
        }
    }
}

// ---------------------------------------------------------------------------
extern "C" void kernel_launch(void* const* d_in, const int* in_sizes, int n_in,
                              void* d_out, int out_size)
{
    const float* query  = (const float*)d_in[0];
    const float* key    = (const float*)d_in[1];
    const float* values = (const float*)d_in[2];
    const float* W_q = (const float*)d_in[3];
    const float* b_q = (const float*)d_in[4];
    const float* W_k = (const float*)d_in[5];
    const float* b_k = (const float*)d_in[6];
    const float* W_v = (const float*)d_in[7];
    const float* b_v = (const float*)d_in[8];
    const float* W_o = (const float*)d_in[9];
    const float* b_o = (const float*)d_in[10];
    float* out = (float*)d_out;

    float *pp;
    __half *xh, *xkh, *xvh, *wqT, *wkT, *wvT, *woT, *qhp, *khp, *vhp, *ah;
    cudaGetSymbolAddress((void**)&pp,  g_part);
    cudaGetSymbolAddress((void**)&xh,  g_xh);
    cudaGetSymbolAddress((void**)&xkh, g_xkh);
    cudaGetSymbolAddress((void**)&xvh, g_xvh);
    cudaGetSymbolAddress((void**)&wqT, g_wqT);
    cudaGetSymbolAddress((void**)&wkT, g_wkT);
    cudaGetSymbolAddress((void**)&wvT, g_wvT);
    cudaGetSymbolAddress((void**)&woT, g_woT);
    cudaGetSymbolAddress((void**)&qhp, g_qh);
    cudaGetSymbolAddress((void**)&khp, g_kh);
    cudaGetSymbolAddress((void**)&vhp, g_vh);
    cudaGetSymbolAddress((void**)&ah,  g_attnh);

    cudaFuncSetAttribute(attn_hmma, cudaFuncAttributeMaxDynamicSharedMemorySize, SMEM_DYN);

    const float scl2 = 0.12753102189093095f;   // log2(e)/sqrt(128)

    // launch 0: fused converts + weight transposes
    prep_all<<<1568, 256>>>(
        (const float4*)query, (const float4*)key, (const float4*)values,
        (uint2*)xh, (uint2*)xkh, (uint2*)xvh,
        W_q, W_k, W_v, W_o, wqT, wkT, wvT, woT);

    // launch 1: all three projections in one grid
    hgemm_qkv<<<1088, 256>>>(xh, xkh, xvh, wqT, wkT, wvT,
                             b_q, b_k, b_v, qhp, khp, vhp, scl2);

    // launch 2: attention — 1024 CTAs of 128 threads, 2 CTAs/SM
    attn_hmma<<<dim3(SS/QROWS, HH, BB), 128, SMEM_DYN>>>(qhp, khp, vhp, ah);

    // launches 3-4: O projection (OSPLIT=8)
    hgemm_splitk<<<dim3(DHH/128, BSZ/128, OSPLIT), 256>>>(ah, woT, pp, BSZ, DHH, NQ);
    reduce_bias<<<(BSZ*DHH/4 + 255)/256, 256>>>(pp, b_o, out, BSZ*DHH, DHH);
}

// round 15
// speedup vs baseline: 1.1473x; 1.1473x over previous
#include <cuda_runtime.h>
#include <cuda_fp16.h>
#include <math.h>
#include <stdint.h>

#define BB 2
#define SS 2048
#define HH 32
#define DHH 128
#define NQ 4096
#define BSZ 4096
#define TK 64
#define NT 32
#define OSPLIT 8

// -------- scratch --------
__device__ float  g_part [OSPLIT*BSZ*DHH];
__device__ __half g_xh   [BSZ*DHH];
__device__ __half g_xkh  [BSZ*DHH];
__device__ __half g_xvh  [BSZ*DHH];
__device__ __half g_wqT  [NQ*DHH];
__device__ __half g_wkT  [DHH*DHH];
__device__ __half g_wvT  [DHH*DHH];
__device__ __half g_woT  [DHH*NQ];
__device__ __half g_qh   [BSZ*NQ];           // Q proj, log2e/sqrt(d) pre-scaled
__device__ __half g_kh   [BSZ*DHH];
__device__ __half g_vh   [BSZ*DHH];
__device__ __half g_attnh[BSZ*NQ];

// -------- helpers --------
__device__ __forceinline__ uint32_t smem_u32(const void* p){
    uint32_t a;
    asm("{ .reg .u64 t; cvta.to.shared.u64 t, %1; cvt.u32.u64 %0, t; }" : "=r"(a) : "l"(p));
    return a;
}
__device__ __forceinline__ void cp16(uint32_t dst, const void* src){
    asm volatile("cp.async.cg.shared.global [%0], [%1], 16;" :: "r"(dst), "l"(src));
}
#define CP_COMMIT() asm volatile("cp.async.commit_group;" ::: "memory")
#define CP_WAIT1()  asm volatile("cp.async.wait_group 1;" ::: "memory")
#define CP_WAIT0()  asm volatile("cp.async.wait_group 0;" ::: "memory")

__device__ __forceinline__ void mma16816(float* c, const uint32_t* a, const uint32_t* b){
    asm volatile("mma.sync.aligned.m16n8k16.row.col.f32.f16.f16.f32 "
        "{%0,%1,%2,%3}, {%4,%5,%6,%7}, {%8,%9}, {%0,%1,%2,%3};"
        : "+f"(c[0]), "+f"(c[1]), "+f"(c[2]), "+f"(c[3])
        : "r"(a[0]), "r"(a[1]), "r"(a[2]), "r"(a[3]), "r"(b[0]), "r"(b[1]));
}
__device__ __forceinline__ void ldsm4(uint32_t* r, uint32_t a){
    asm volatile("ldmatrix.sync.aligned.m8n8.x4.shared.b16 {%0,%1,%2,%3}, [%4];"
        : "=r"(r[0]), "=r"(r[1]), "=r"(r[2]), "=r"(r[3]) : "r"(a));
}
__device__ __forceinline__ void ldsm4t(uint32_t* r, uint32_t a){
    asm volatile("ldmatrix.sync.aligned.m8n8.x4.trans.shared.b16 {%0,%1,%2,%3}, [%4];"
        : "=r"(r[0]), "=r"(r[1]), "=r"(r[2]), "=r"(r[3]) : "r"(a));
}
__device__ __forceinline__ uint32_t packh2(float x, float y){
    __half2 h = __floats2half2_rn(x, y);
    return *reinterpret_cast<uint32_t*>(&h);
}
__device__ __forceinline__ uint32_t ex2x2(uint32_t h){
    uint32_t r;
    asm("ex2.approx.f16x2 %0, %1;" : "=r"(r) : "r"(h));
    return r;
}
__device__ __forceinline__ float sumh2(uint32_t h){
    __half2 v = *reinterpret_cast<__half2*>(&h);
    float2 f = __half22float2(v);
    return f.x + f.y;
}

// =======================================================================
// Fused prep: input converts (blocks 0..511) + weight transposes (512..1567)
// =======================================================================
__global__ __launch_bounds__(256) void prep_all(
    const float4* __restrict__ q, const float4* __restrict__ k, const float4* __restrict__ v,
    uint2* __restrict__ oq, uint2* __restrict__ ok, uint2* __restrict__ ov,
    const float* __restrict__ Wq, const float* __restrict__ Wk,
    const float* __restrict__ Wv, const float* __restrict__ Wo,
    __half* __restrict__ wqT, __half* __restrict__ wkT,
    __half* __restrict__ wvT, __half* __restrict__ woT)
{
    __shared__ float t[32][33];
    int id = blockIdx.x;
    if (id < 512) {
        int i = id * 256 + threadIdx.x;
        float4 f;
        f = q[i]; oq[i] = make_uint2(packh2(f.x, f.y), packh2(f.z, f.w));
        f = k[i]; ok[i] = make_uint2(packh2(f.x, f.y), packh2(f.z, f.w));
        f = v[i]; ov[i] = make_uint2(packh2(f.x, f.y), packh2(f.z, f.w));
        return;
    }
    id -= 512;
    const float* in; __half* out; int K, N, tile;
    if (id < 512)      { in = Wq; out = wqT; K = DHH; N = NQ;  tile = id; }
    else if (id < 528) { in = Wk; out = wkT; K = DHH; N = DHH; tile = id - 512; }
    else if (id < 544) { in = Wv; out = wvT; K = DHH; N = DHH; tile = id - 528; }
    else               { in = Wo; out = woT; K = NQ;  N = DHH; tile = id - 544; }
    int ntx = N / 32;
    int bx = (tile % ntx) * 32, by = (tile / ntx) * 32;
    int x = threadIdx.x & 31, y = threadIdx.x >> 5;
    #pragma unroll
    for (int i = 0; i < 4; ++i)
        t[y + 8*i][x] = in[(size_t)(by + y + 8*i)*N + bx + x];
    __syncthreads();
    #pragma unroll
    for (int i = 0; i < 4; ++i)
        out[(size_t)(bx + y + 8*i)*K + by + x] = __float2half_rn(t[x][y + 8*i]);
}

// =======================================================================
// Fused Q/K/V projections: one launch, flat grid of 1088 CTAs.
// =======================================================================
__global__ __launch_bounds__(256) void hgemm_qkv(
    const __half* __restrict__ xq, const __half* __restrict__ xk, const __half* __restrict__ xv,
    const __half* __restrict__ wqT, const __half* __restrict__ wkT, const __half* __restrict__ wvT,
    const float* __restrict__ b_q, const float* __restrict__ b_k, const float* __restrict__ b_v,
    __half* __restrict__ qh, __half* __restrict__ kh, __half* __restrict__ vh,
    float scl2)
{
    __shared__ __align__(16) __half As[2][128*40];
    __shared__ __align__(16) __half Bs[2][128*40];

    const int bid = blockIdx.x;
    const __half *A, *Bt; const float* bias; __half* C; int N, m0, n0; float scale;
    if (bid < 1024) {
        A = xq; Bt = wqT; bias = b_q; C = qh; N = NQ; scale = scl2;
        m0 = (bid >> 5) * 128; n0 = (bid & 31) * 128;
    } else if (bid < 1056) {
        A = xk; Bt = wkT; bias = b_k; C = kh; N = DHH; scale = 1.0f;
        m0 = (bid - 1024) * 128; n0 = 0;
    } else {
        A = xv; Bt = wvT; bias = b_v; C = vh; N = DHH; scale = 1.0f;
        m0 = (bid - 1056) * 128; n0 = 0;
    }

    const int tid = threadIdx.x, lane = tid & 31, w = tid >> 5;
    const int wm = (w >> 2) * 64, wn = (w & 3) * 32;
    const int g = lane >> 2, q4 = lane & 3;
    const int arow = ((lane >> 3) & 1) * 8 + (lane & 7);
    const int akse = (lane >> 4) * 8;
    const int brow = ((lane >> 4) & 1) * 8 + (lane & 7);
    const int bkse = ((lane >> 3) & 1) * 8;

    float acc[4][4][4] = {};

    auto load = [&](int kb, int st){
        #pragma unroll
        for (int i = 0; i < 2; ++i) {
            int e = tid + 256*i, r = e >> 2, c = e & 3;
            cp16(smem_u32(&As[st][r*40 + c*8]), A  + (size_t)(m0 + r)*DHH + kb*32 + c*8);
            cp16(smem_u32(&Bs[st][r*40 + c*8]), Bt + (size_t)(n0 + r)*DHH + kb*32 + c*8);
        }
    };
    load(0, 0); CP_COMMIT();

    #pragma unroll
    for (int kb = 0; kb < 4; ++kb) {
        if (kb + 1 < 4) { load(kb+1, (kb+1)&1); CP_COMMIT(); CP_WAIT1(); }
        else            { CP_WAIT0(); }
        __syncthreads();
        const int st = kb & 1;
        const uint32_t aB = smem_u32(&As[st][0]) + (wm + arow)*80 + akse*2;
        const uint32_t bB = smem_u32(&Bs[st][0]) + (wn + brow)*80 + bkse*2;
        #pragma unroll
        for (int ks = 0; ks < 2; ++ks) {
            uint32_t aF[4][4], bF[2][4];
            #pragma unroll
            for (int mi = 0; mi < 4; ++mi) ldsm4(aF[mi], aB + mi*16*80 + ks*32);
            #pragma unroll
            for (int np = 0; np < 2; ++np) ldsm4(bF[np], bB + np*16*80 + ks*32);
            #pragma unroll
            for (int mi = 0; mi < 4; ++mi)
                #pragma unroll
                for (int ni = 0; ni < 4; ++ni)
                    mma16816(acc[mi][ni], aF[mi], bF[ni>>1] + (ni&1)*2);
        }
        __syncthreads();
    }

    #pragma unroll
    for (int mi = 0; mi < 4; ++mi)
        #pragma unroll
        for (int ni = 0; ni < 4; ++ni) {
            int row = m0 + wm + mi*16 + g;
            int col = n0 + wn + ni*8 + 2*q4;
            float b0 = bias[col], b1 = bias[col+1];
            *reinterpret_cast<__half2*>(C + (size_t)row*N + col) =
                __floats2half2_rn((acc[mi][ni][0] + b0)*scale, (acc[mi][ni][1] + b1)*scale);
            *reinterpret_cast<__half2*>(C + (size_t)(row+8)*N + col) =
                __floats2half2_rn((acc[mi][ni][2] + b0)*scale, (acc[mi][ni][3] + b1)*scale);
        }
}

// ---- split-K hgemm (O projection): 3-stage cp.async, single sync/iter ----
__global__ __launch_bounds__(256) void hgemm_splitk(
    const __half* __restrict__ A, const __half* __restrict__ Bt,
    float* __restrict__ part, int M, int N, int K)
{
    __shared__ __align__(16) __half As[3][128*40];
    __shared__ __align__(16) __half Bs[3][128*40];
    const int tid = threadIdx.x, lane = tid & 31, w = tid >> 5;
    const int wm = (w >> 2) * 64, wn = (w & 3) * 32;
    const int m0 = blockIdx.y * 128, n0 = blockIdx.x * 128;
    const int kc = blockIdx.z;
    const int g = lane >> 2, q4 = lane & 3;
    const int arow = ((lane >> 3) & 1) * 8 + (lane & 7);
    const int akse = (lane >> 4) * 8;
    const int brow = ((lane >> 4) & 1) * 8 + (lane & 7);
    const int bkse = ((lane >> 3) & 1) * 8;

    float acc[4][4][4] = {};
    const int nkpc = K / 32 / OSPLIT;     // 16
    const int kb0 = kc * nkpc;

    auto load = [&](int kb, int st){
        #pragma unroll
        for (int i = 0; i < 2; ++i) {
            int e = tid + 256*i, r = e >> 2, c = e & 3;
            cp16(smem_u32(&As[st][r*40 + c*8]), A  + (size_t)(m0 + r)*K + kb*32 + c*8);
            cp16(smem_u32(&Bs[st][r*40 + c*8]), Bt + (size_t)(n0 + r)*K + kb*32 + c*8);
        }
    };
    load(kb0, 0); CP_COMMIT();
    load(kb0 + 1, 1); CP_COMMIT();

    for (int i = 0; i < nkpc; ++i) {
        if (i + 1 < nkpc) { CP_WAIT1(); } else { CP_WAIT0(); }
        __syncthreads();                                // stage i%3 ready, prior reads done
        if (i + 2 < nkpc) { load(kb0 + i + 2, (i + 2) % 3); CP_COMMIT(); }

        const int st = i % 3;
        const uint32_t aB = smem_u32(&As[st][0]) + (wm + arow)*80 + akse*2;
        const uint32_t bB = smem_u32(&Bs[st][0]) + (wn + brow)*80 + bkse*2;
        #pragma unroll
        for (int ks = 0; ks < 2; ++ks) {
            uint32_t aF[4][4], bF[2][4];
            #pragma unroll
            for (int mi = 0; mi < 4; ++mi) ldsm4(aF[mi], aB + mi*16*80 + ks*32);
            #pragma unroll
            for (int np = 0; np < 2; ++np) ldsm4(bF[np], bB + np*16*80 + ks*32);
            #pragma unroll
            for (int mi = 0; mi < 4; ++mi)
                #pragma unroll
                for (int ni = 0; ni < 4; ++ni)
                    mma16816(acc[mi][ni], aF[mi], bF[ni>>1] + (ni&1)*2);
        }
    }

    float* P = part + (size_t)kc * M * N;
    #pragma unroll
    for (int mi = 0; mi < 4; ++mi)
        #pragma unroll
        for (int ni = 0; ni < 4; ++ni) {
            int row = m0 + wm + mi*16 + g;
            int col = n0 + wn + ni*8 + 2*q4;
            *reinterpret_cast<float2*>(P + (size_t)row*N + col)     = make_float2(acc[mi][ni][0], acc[mi][ni][1]);
            *reinterpret_cast<float2*>(P + (size_t)(row+8)*N + col) = make_float2(acc[mi][ni][2], acc[mi][ni][3]);
        }
}

__global__ void reduce_bias(const float* __restrict__ part, const float* __restrict__ bias,
                            float* __restrict__ out, int MN, int N)
{
    int i = (blockIdx.x * 256 + threadIdx.x) * 4;
    if (i >= MN) return;
    float4 s = *reinterpret_cast<const float4*>(part + i);
    #pragma unroll
    for (int kc = 1; kc < OSPLIT; ++kc) {
        float4 p = *reinterpret_cast<const float4*>(part + (size_t)kc*MN + i);
        s.x += p.x; s.y += p.y; s.z += p.z; s.w += p.w;
    }
    int c = i & (N - 1);
    s.x += bias[c]; s.y += bias[c+1]; s.z += bias[c+2]; s.w += bias[c+3];
    *reinterpret_cast<float4*>(out + i) = s;
}

// =======================================================================
// HMMA flash attention — exact R12 structure (best measured):
// 4 warps/CTA, M=32/warp, Q in smem, 2-stage K/V, 2 CTAs/SM,
// rowsum on FMA pipe.
// =======================================================================
#define KROWB 272
#define KBYTES (64*KROWB)
#define BUF    (2*KBYTES)             // K+V one stage: 34816
#define QROWB  272
#define QROWS  128
#define QBYTES (QROWS*QROWB)          // 34816
#define SMEM_DYN (QBYTES + 2*BUF)     // 104448 -> 2 CTAs/SM

__device__ __forceinline__ void load_tile(uint32_t buf, int b, int kt,
    const __half* kh, const __half* vh, int tid)
{
    const __half* ks = kh + ((size_t)b*SS + (size_t)kt*TK) * DHH;
    const __half* vs = vh + ((size_t)b*SS + (size_t)kt*TK) * DHH;
    #pragma unroll
    for (int t = 0; t < 8; ++t) {
        int e = tid + t*128, r = e >> 4, c = e & 15;
        cp16(buf + r*KROWB + c*16,          ks + (size_t)r*DHH + c*8);
        cp16(buf + KBYTES + r*KROWB + c*16, vs + (size_t)r*DHH + c*8);
    }
}

__global__ __launch_bounds__(128, 2) void attn_hmma(
    const __half* __restrict__ qh, const __half* __restrict__ kh,
    const __half* __restrict__ vh, __half* __restrict__ o2h)
{
    extern __shared__ __align__(16) char smraw[];
    const uint32_t smb = smem_u32(smraw);
    const uint32_t kvb = smb + QBYTES;
    const int qb = blockIdx.x, h = blockIdx.y, b = blockIdx.z;
    const int tid = threadIdx.x, w = tid >> 5, lane = tid & 31;
    const int g = lane >> 2, q4 = lane & 3;
    const int jrow = ((lane >> 4) & 1) * 8 + (lane & 7);
    const int ksel = ((lane >> 3) & 1) * 8;
    const int arow = ((lane >> 3) & 1) * 8 + (lane & 7);
    const int akse = (lane >> 4) * 8;
    const int vrow = lane & 15;
    const int vcol8 = (lane >> 4) * 8;

    {
        const __half* qsrc = qh + ((size_t)b*SS + (size_t)h*64 + (size_t)qb*4) * NQ;
        #pragma unroll
        for (int t = 0; t < 16; ++t) {
            int e = tid + t*128, r = e >> 4, c = e & 15;
            cp16(smb + r*QROWB + c*16, qsrc + (size_t)r*DHH + c*8);
        }
    }
    load_tile(kvb, b, 0, kh, vh, tid);
    CP_COMMIT();
    load_tile(kvb + BUF, b, 1, kh, vh, tid);
    CP_COMMIT();

    float o[2][16][4];
    #pragma unroll
    for (int m = 0; m < 2; ++m)
        #pragma unroll
        for (int n = 0; n < 16; ++n)
            #pragma unroll
            for (int i = 0; i < 4; ++i) o[m][n][i] = 0.f;
    float rs[2][2] = {};
    const uint32_t Qb = smb + (w*32 + arow)*QROWB + akse*2;

    for (int kt = 0; kt < NT; ++kt) {
        if (kt + 1 < NT) { CP_WAIT1(); } else { CP_WAIT0(); }
        __syncthreads();

        const uint32_t Kb = kvb + (uint32_t)(kt&1)*BUF + jrow*KROWB + ksel*2;
        const uint32_t Vb = kvb + (uint32_t)(kt&1)*BUF + KBYTES + vrow*KROWB + vcol8*2;

        // S = Q K^T for both m-tiles (K fragments shared)
        float s[2][8][4];
        #pragma unroll
        for (int m = 0; m < 2; ++m)
            #pragma unroll
            for (int j = 0; j < 8; ++j)
                #pragma unroll
                for (int i = 0; i < 4; ++i) s[m][j][i] = 0.f;
        #pragma unroll
        for (int ks = 0; ks < 8; ++ks) {
            uint32_t aF0[4], aF1[4];
            ldsm4(aF0, Qb + 32*ks);
            ldsm4(aF1, Qb + 16*QROWB + 32*ks);
            uint32_t bb[2][4];
            ldsm4(bb[0], Kb + 32*ks);
            #pragma unroll
            for (int jp = 0; jp < 4; ++jp) {
                if (jp < 3) ldsm4(bb[(jp+1)&1], Kb + (jp+1)*16*KROWB + 32*ks);
                mma16816(s[0][2*jp],   aF0, bb[jp&1]);
                mma16816(s[0][2*jp+1], aF0, bb[jp&1] + 2);
                mma16816(s[1][2*jp],   aF1, bb[jp&1]);
                mma16816(s[1][2*jp+1], aF1, bb[jp&1] + 2);
            }
        }

        // P = 2^S (fp16x2 MUFU); rowsum accumulated in fp32 on FMA pipe
        uint32_t P[2][4][4];
        #pragma unroll
        for (int m = 0; m < 2; ++m)
            #pragma unroll
            for (int j = 0; j < 8; ++j) {
                uint32_t p0 = ex2x2(packh2(s[m][j][0], s[m][j][1]));
                uint32_t p1 = ex2x2(packh2(s[m][j][2], s[m][j][3]));
                P[m][j>>1][(j&1)*2]     = p0;
                P[m][j>>1][(j&1)*2 + 1] = p1;
                rs[m][0] += sumh2(p0);
                rs[m][1] += sumh2(p1);
            }

        // O += P V
        #pragma unroll
        for (int ks = 0; ks < 4; ++ks) {
            const uint32_t Vk = Vb + ks*16*KROWB;
            uint32_t bb[2][4];
            ldsm4t(bb[0], Vk);
            #pragma unroll
            for (int np = 0; np < 8; ++np) {
                if (np < 7) ldsm4t(bb[(np+1)&1], Vk + (np+1)*32);
                mma16816(o[0][2*np],   P[0][ks], bb[np&1]);
                mma16816(o[0][2*np+1], P[0][ks], bb[np&1] + 2);
                mma16816(o[1][2*np],   P[1][ks], bb[np&1]);
                mma16816(o[1][2*np+1], P[1][ks], bb[np&1] + 2);
            }
        }

        __syncthreads();
        if (kt + 2 < NT) {
            load_tile(kvb + (uint32_t)(kt&1)*BUF, b, kt+2, kh, vh, tid);
            CP_COMMIT();
        }
    }

    // cross-lane rowsum reduce (4 lanes per row)
    #pragma unroll
    for (int m = 0; m < 2; ++m)
        #pragma unroll
        for (int r = 0; r < 2; ++r) {
            rs[m][r] += __shfl_xor_sync(0xffffffffu, rs[m][r], 1);
            rs[m][r] += __shfl_xor_sync(0xffffffffu, rs[m][r], 2);
        }

    // epilogue: rows = qb*128 + w*32 + m*16 + {g, g+8}
    #pragma unroll
    for (int m = 0; m < 2; ++m) {
        const float inv0 = 1.0f / rs[m][0], inv1 = 1.0f / rs[m][1];
        const int lr = w*32 + m*16 + g;
        __half* dst0 = o2h + ((size_t)b*SS + (size_t)qb*QROWS + lr)     * NQ + (size_t)h * DHH;
        __half* dst1 = o2h + ((size_t)b*SS + (size_t)qb*QROWS + lr + 8) * NQ + (size_t)h * DHH;
        #pragma unroll
        for (int n = 0; n < 16; ++n) {
            int c = 8*n + 2*q4;
            *reinterpret_cast<__half2*>(dst0 + c) = __floats2half2_rn(o[m][n][0]*inv0, o[m][n][1]*inv0);
            *reinterpret_cast<__half2*>(dst1 + c) = __floats2half2_rn(o[m][n][2]*inv1, o[m][n][3]*inv1);
        }
    }
}

// ---------------------------------------------------------------------------
extern "C" void kernel_launch(void* const* d_in, const int* in_sizes, int n_in,
                              void* d_out, int out_size)
{
    const float* query  = (const float*)d_in[0];
    const float* key    = (const float*)d_in[1];
    const float* values = (const float*)d_in[2];
    const float* W_q = (const float*)d_in[3];
    const float* b_q = (const float*)d_in[4];
    const float* W_k = (const float*)d_in[5];
    const float* b_k = (const float*)d_in[6];
    const float* W_v = (const float*)d_in[7];
    const float* b_v = (const float*)d_in[8];
    const float* W_o = (const float*)d_in[9];
    const float* b_o = (const float*)d_in[10];
    float* out = (float*)d_out;

    float *pp;
    __half *xh, *xkh, *xvh, *wqT, *wkT, *wvT, *woT, *qhp, *khp, *vhp, *ah;
    cudaGetSymbolAddress((void**)&pp,  g_part);
    cudaGetSymbolAddress((void**)&xh,  g_xh);
    cudaGetSymbolAddress((void**)&xkh, g_xkh);
    cudaGetSymbolAddress((void**)&xvh, g_xvh);
    cudaGetSymbolAddress((void**)&wqT, g_wqT);
    cudaGetSymbolAddress((void**)&wkT, g_wkT);
    cudaGetSymbolAddress((void**)&wvT, g_wvT);
    cudaGetSymbolAddress((void**)&woT, g_woT);
    cudaGetSymbolAddress((void**)&qhp, g_qh);
    cudaGetSymbolAddress((void**)&khp, g_kh);
    cudaGetSymbolAddress((void**)&vhp, g_vh);
    cudaGetSymbolAddress((void**)&ah,  g_attnh);

    cudaFuncSetAttribute(attn_hmma, cudaFuncAttributeMaxDynamicSharedMemorySize, SMEM_DYN);

    const float scl2 = 0.12753102189093095f;   // log2(e)/sqrt(128)

    // launch 0: fused converts + weight transposes
    prep_all<<<1568, 256>>>(
        (const float4*)query, (const float4*)key, (const float4*)values,
        (uint2*)xh, (uint2*)xkh, (uint2*)xvh,
        W_q, W_k, W_v, W_o, wqT, wkT, wvT, woT);

    // launch 1: all three projections in one grid
    hgemm_qkv<<<1088, 256>>>(xh, xkh, xvh, wqT, wkT, wvT,
                             b_q, b_k, b_v, qhp, khp, vhp, scl2);

    // launch 2: attention — 1024 CTAs of 128 threads, 2 CTAs/SM
    attn_hmma<<<dim3(SS/QROWS, HH, BB), 128, SMEM_DYN>>>(qhp, khp, vhp, ah);

    // launches 3-4: O projection (OSPLIT=8, 3-stage pipeline)
    hgemm_splitk<<<dim3(DHH/128, BSZ/128, OSPLIT), 256>>>(ah, woT, pp, BSZ, DHH, NQ);
    reduce_bias<<<(BSZ*DHH/4 + 255)/256, 256>>>(pp, b_o, out, BSZ*DHH, DHH);
}